// round 1
// baseline (speedup 1.0000x reference)
#include <cuda_runtime.h>
#include <math.h>

// ---------------- problem constants ----------------
constexpr int N_TOK  = 2048 * 64;   // 131072 tokens
constexpr int EMB    = 384;         // C
constexpr int NHEAD  = 8;
constexpr int HSZ    = 48;          // head size
constexpr int SEQ    = 64;          // T (attention window, per batch)
constexpr int FF     = 1536;        // 4*C
constexpr float ATT_SCALE = 2.449489742783178f; // HEAD_SIZE * C^-0.5

// ---------------- scratch (static device memory, no allocations) ----------------
__device__ __align__(128) float g_h   [(size_t)N_TOK * EMB];       // LN1 out
__device__ __align__(128) float g_qkv [(size_t)N_TOK * 3 * EMB];   // [tok][1152]: q|k|v, col = h*48+d
__device__ __align__(128) float g_attn[(size_t)N_TOK * EMB];       // attention out (concat heads)
__device__ __align__(128) float g_x2  [(size_t)N_TOK * EMB];       // post-attn residual
__device__ __align__(128) float g_h2  [(size_t)N_TOK * EMB];       // LN2 out
__device__ __align__(128) float g_hid [(size_t)N_TOK * FF];        // MLP hidden
__device__ __align__(128) float g_Wqkv[EMB * 3 * EMB];             // transposed qkv weights [c][1152]

// ---------------- f32x2 packed math helpers ----------------
__device__ __forceinline__ unsigned long long pk2(float lo, float hi) {
    unsigned long long r;
    asm("mov.b64 %0, {%1, %2};" : "=l"(r) : "f"(lo), "f"(hi));
    return r;
}
__device__ __forceinline__ float2 upk2(unsigned long long p) {
    float2 r;
    asm("mov.b64 {%0, %1}, %2;" : "=f"(r.x), "=f"(r.y) : "l"(p));
    return r;
}
#define FMA2(d, a, b) asm volatile("fma.rn.f32x2 %0, %1, %2, %0;" : "+l"(d) : "l"(a), "l"(b))

// ---------------- weight prep: [H,C,D] -> [C, H*D] for q,k,v concatenated ----------------
__global__ void prep_w_kernel(const float* __restrict__ Wq,
                              const float* __restrict__ Wk,
                              const float* __restrict__ Wv) {
    int i = blockIdx.x * blockDim.x + threadIdx.x;  // over H*C*D
    if (i >= NHEAD * EMB * HSZ) return;
    int h = i / (EMB * HSZ);
    int r = i % (EMB * HSZ);
    int c = r / HSZ;
    int d = r % HSZ;
    int col = h * HSZ + d;
    g_Wqkv[(size_t)c * (3 * EMB) + col]            = Wq[i];
    g_Wqkv[(size_t)c * (3 * EMB) + EMB + col]      = Wk[i];
    g_Wqkv[(size_t)c * (3 * EMB) + 2 * EMB + col]  = Wv[i];
}

// ---------------- layernorm: one block (96 threads) per row of 384 ----------------
__global__ void ln_kernel(const float* __restrict__ in,
                          const float* __restrict__ g,
                          const float* __restrict__ b,
                          float* __restrict__ out) {
    int row = blockIdx.x;
    int t = threadIdx.x;  // 0..95, each handles one float4 (96*4 = 384)
    const float4* in4 = (const float4*)(in + (size_t)row * EMB);
    float4 v = in4[t];
    float s  = v.x + v.y + v.z + v.w;
    float ss = v.x * v.x + v.y * v.y + v.z * v.z + v.w * v.w;
    #pragma unroll
    for (int off = 16; off > 0; off >>= 1) {
        s  += __shfl_down_sync(0xffffffffu, s, off);
        ss += __shfl_down_sync(0xffffffffu, ss, off);
    }
    __shared__ float red0[3], red1[3];
    int w = t >> 5, l = t & 31;
    if (l == 0) { red0[w] = s; red1[w] = ss; }
    __syncthreads();
    float S  = red0[0] + red0[1] + red0[2];
    float SS = red1[0] + red1[1] + red1[2];
    float mu  = S * (1.0f / EMB);
    float var = SS * (1.0f / EMB) - mu * mu;
    float rs = rsqrtf(var + 1e-5f);
    float4 gv = ((const float4*)g)[t];
    float4 bv = ((const float4*)b)[t];
    float4 o;
    o.x = (v.x - mu) * rs * gv.x + bv.x;
    o.y = (v.y - mu) * rs * gv.y + bv.y;
    o.z = (v.z - mu) * rs * gv.z + bv.z;
    o.w = (v.w - mu) * rs * gv.w + bv.w;
    ((float4*)(out + (size_t)row * EMB))[t] = o;
}

// ---------------- fp32 register-tiled GEMM with f32x2 packed FMA ----------------
// out[M,Nc] = A[M,K] @ W[K,Nc] (+bias) (+res) (relu?)
// BM=BN=128, BK=16, 256 threads, 8x8 per thread. All dims divide the tiles exactly.
template<bool BIAS, bool RES, bool RELU>
__global__ void __launch_bounds__(256)
gemm_kernel(const float* __restrict__ A, const float* __restrict__ W,
            const float* __restrict__ bias, const float* __restrict__ res,
            float* __restrict__ out, int M, int K, int Nc) {
    constexpr int BM = 128, BN = 128, BK = 16;
    __shared__ float As[BK][BM];
    __shared__ float Ws[BK][BN];
    const int tid = threadIdx.x;
    const int m0 = blockIdx.y * BM;
    const int n0 = blockIdx.x * BN;
    const int tx = tid & 15;   // N direction
    const int ty = tid >> 4;   // M direction

    unsigned long long acc[8][4];
    #pragma unroll
    for (int i = 0; i < 8; i++)
        #pragma unroll
        for (int j = 0; j < 4; j++) acc[i][j] = 0ull;

    for (int k0 = 0; k0 < K; k0 += BK) {
        // A tile: 128 rows x 16 k, loaded as float4, stored transposed
        #pragma unroll
        for (int ii = 0; ii < 2; ii++) {
            int idx = tid * 2 + ii;          // 0..511
            int row = idx >> 2, kq = idx & 3;
            float4 a = *(const float4*)(A + (size_t)(m0 + row) * K + k0 + kq * 4);
            As[kq * 4 + 0][row] = a.x;
            As[kq * 4 + 1][row] = a.y;
            As[kq * 4 + 2][row] = a.z;
            As[kq * 4 + 3][row] = a.w;
        }
        // W tile: 16 k x 128 cols
        #pragma unroll
        for (int ii = 0; ii < 2; ii++) {
            int idx = tid * 2 + ii;
            int kr = idx >> 5, nc = idx & 31;
            *(float4*)(&Ws[kr][nc * 4]) =
                *(const float4*)(W + (size_t)(k0 + kr) * Nc + n0 + nc * 4);
        }
        __syncthreads();
        #pragma unroll
        for (int k = 0; k < BK; k++) {
            float4 a0 = *(const float4*)(&As[k][ty * 8]);
            float4 a1 = *(const float4*)(&As[k][ty * 8 + 4]);
            float4 w0 = *(const float4*)(&Ws[k][tx * 8]);
            float4 w1 = *(const float4*)(&Ws[k][tx * 8 + 4]);
            unsigned long long wp[4] = { pk2(w0.x, w0.y), pk2(w0.z, w0.w),
                                         pk2(w1.x, w1.y), pk2(w1.z, w1.w) };
            float av[8] = {a0.x, a0.y, a0.z, a0.w, a1.x, a1.y, a1.z, a1.w};
            #pragma unroll
            for (int i = 0; i < 8; i++) {
                unsigned long long ap = pk2(av[i], av[i]);
                FMA2(acc[i][0], ap, wp[0]);
                FMA2(acc[i][1], ap, wp[1]);
                FMA2(acc[i][2], ap, wp[2]);
                FMA2(acc[i][3], ap, wp[3]);
            }
        }
        __syncthreads();
    }

    float bvals[8];
    if (BIAS) {
        #pragma unroll
        for (int j = 0; j < 8; j++) bvals[j] = bias[n0 + tx * 8 + j];
    }
    #pragma unroll
    for (int i = 0; i < 8; i++) {
        int row = m0 + ty * 8 + i;
        float o[8];
        #pragma unroll
        for (int j = 0; j < 4; j++) {
            float2 f = upk2(acc[i][j]);
            o[2 * j] = f.x; o[2 * j + 1] = f.y;
        }
        if (BIAS) {
            #pragma unroll
            for (int j = 0; j < 8; j++) o[j] += bvals[j];
        }
        if (RES) {
            const float4* rp = (const float4*)(res + (size_t)row * Nc + n0 + tx * 8);
            float4 r0 = rp[0], r1 = rp[1];
            o[0] += r0.x; o[1] += r0.y; o[2] += r0.z; o[3] += r0.w;
            o[4] += r1.x; o[5] += r1.y; o[6] += r1.z; o[7] += r1.w;
        }
        if (RELU) {
            #pragma unroll
            for (int j = 0; j < 8; j++) o[j] = fmaxf(o[j], 0.0f);
        }
        float4* op = (float4*)(out + (size_t)row * Nc + n0 + tx * 8);
        op[0] = make_float4(o[0], o[1], o[2], o[3]);
        op[1] = make_float4(o[4], o[5], o[6], o[7]);
    }
}

// ---------------- attention: one block per (batch, head), 64 threads = 64 query rows ----------------
__global__ void attn_kernel(const float* __restrict__ qkv, float* __restrict__ out) {
    int b = blockIdx.x, h = blockIdx.y;
    int t = threadIdx.x;  // 0..63 query row
    __shared__ float ks[SEQ][HSZ];
    __shared__ float vs[SEQ][HSZ];
    __shared__ float ps[SEQ][SEQ + 1];

    const float* base = qkv + (size_t)(b * SEQ + t) * (3 * EMB) + h * HSZ;
    float qreg[HSZ];
    #pragma unroll
    for (int i = 0; i < HSZ / 4; i++) {
        float4 qv = *(const float4*)(base + i * 4);
        qreg[4 * i] = qv.x; qreg[4 * i + 1] = qv.y;
        qreg[4 * i + 2] = qv.z; qreg[4 * i + 3] = qv.w;
        *(float4*)(&ks[t][4 * i]) = *(const float4*)(base + EMB + i * 4);
        *(float4*)(&vs[t][4 * i]) = *(const float4*)(base + 2 * EMB + i * 4);
    }
    __syncthreads();

    // scores (causal) + running max
    float mx = -1e30f;
    for (int s = 0; s <= t; s++) {
        float acc = 0.0f;
        #pragma unroll
        for (int d = 0; d < HSZ; d++) acc += qreg[d] * ks[s][d];
        acc *= ATT_SCALE;
        ps[t][s] = acc;
        mx = fmaxf(mx, acc);
    }
    // softmax
    float sum = 0.0f;
    for (int s = 0; s <= t; s++) {
        float e = __expf(ps[t][s] - mx);
        ps[t][s] = e;
        sum += e;
    }
    float inv = 1.0f / sum;
    // attn @ V
    float oacc[HSZ];
    #pragma unroll
    for (int d = 0; d < HSZ; d++) oacc[d] = 0.0f;
    for (int s = 0; s <= t; s++) {
        float p = ps[t][s] * inv;
        #pragma unroll
        for (int d = 0; d < HSZ; d++) oacc[d] += p * vs[s][d];
    }
    float* op = out + (size_t)(b * SEQ + t) * EMB + h * HSZ;
    #pragma unroll
    for (int i = 0; i < HSZ / 4; i++)
        *(float4*)(op + 4 * i) = make_float4(oacc[4 * i], oacc[4 * i + 1],
                                             oacc[4 * i + 2], oacc[4 * i + 3]);
}

// ---------------- launch ----------------
extern "C" void kernel_launch(void* const* d_in, const int* in_sizes, int n_in,
                              void* d_out, int out_size) {
    const float* x     = (const float*)d_in[0];
    const float* ln1_g = (const float*)d_in[1];
    const float* ln1_b = (const float*)d_in[2];
    const float* ln2_g = (const float*)d_in[3];
    const float* ln2_b = (const float*)d_in[4];
    const float* Wq    = (const float*)d_in[5];
    const float* Wk    = (const float*)d_in[6];
    const float* Wv    = (const float*)d_in[7];
    const float* Wp    = (const float*)d_in[8];
    const float* bp    = (const float*)d_in[9];
    const float* W1    = (const float*)d_in[10];
    const float* b1    = (const float*)d_in[11];
    const float* W2    = (const float*)d_in[12];
    const float* b2    = (const float*)d_in[13];
    float* out = (float*)d_out;

    float *h, *qkv, *attn, *x2, *h2, *hid, *wqkv;
    cudaGetSymbolAddress((void**)&h,    g_h);
    cudaGetSymbolAddress((void**)&qkv,  g_qkv);
    cudaGetSymbolAddress((void**)&attn, g_attn);
    cudaGetSymbolAddress((void**)&x2,   g_x2);
    cudaGetSymbolAddress((void**)&h2,   g_h2);
    cudaGetSymbolAddress((void**)&hid,  g_hid);
    cudaGetSymbolAddress((void**)&wqkv, g_Wqkv);

    // 0) weight prep (cheap, deterministic)
    prep_w_kernel<<<(NHEAD * EMB * HSZ + 255) / 256, 256>>>(Wq, Wk, Wv);
    // 1) LN1
    ln_kernel<<<N_TOK, 96>>>(x, ln1_g, ln1_b, h);
    // 2) fused QKV GEMM: [N,384] x [384,1152]
    gemm_kernel<false, false, false><<<dim3((3 * EMB) / 128, N_TOK / 128), 256>>>(
        h, wqkv, nullptr, nullptr, qkv, N_TOK, EMB, 3 * EMB);
    // 3) attention per (b, h)
    attn_kernel<<<dim3(2048, NHEAD), SEQ>>>(qkv, attn);
    // 4) proj + bias + residual(x)
    gemm_kernel<true, true, false><<<dim3(EMB / 128, N_TOK / 128), 256>>>(
        attn, Wp, bp, x, x2, N_TOK, EMB, EMB);
    // 5) LN2
    ln_kernel<<<N_TOK, 96>>>(x2, ln2_g, ln2_b, h2);
    // 6) MLP up + relu
    gemm_kernel<true, false, true><<<dim3(FF / 128, N_TOK / 128), 256>>>(
        h2, W1, b1, nullptr, hid, N_TOK, EMB, FF);
    // 7) MLP down + bias + residual(x2) -> out
    gemm_kernel<true, true, false><<<dim3(EMB / 128, N_TOK / 128), 256>>>(
        hid, W2, b2, x2, out, N_TOK, FF, EMB);
}

// round 3
// speedup vs baseline: 1.8322x; 1.8322x over previous
#include <cuda_runtime.h>
#include <cuda_bf16.h>
#include <cstdint>

// ---------------- problem constants ----------------
constexpr int N_TOK  = 2048 * 64;   // 131072 tokens
constexpr int EMB    = 384;
constexpr int NHEAD  = 8;
constexpr int HSZ    = 48;
constexpr int SEQ    = 64;
constexpr int FF     = 1536;
constexpr float ATT_SCALE = 2.449489742783178f;

// ---------------- scratch (static device memory) ----------------
__device__ __align__(128) __nv_bfloat16 g_ln1 [(size_t)N_TOK * 2 * EMB];   // [hi|lo]
__device__ __align__(128) float         g_qkv [(size_t)N_TOK * 3 * EMB];   // fp32 q|k|v
__device__ __align__(128) __nv_bfloat16 g_attn[(size_t)N_TOK * 2 * EMB];   // [hi|lo]
__device__ __align__(128) float         g_x2  [(size_t)N_TOK * EMB];       // fp32 residual
__device__ __align__(128) __nv_bfloat16 g_h2  [(size_t)N_TOK * 2 * EMB];   // [hi|lo]
__device__ __align__(128) __nv_bfloat16 g_hid [(size_t)N_TOK * 2 * FF];    // [hi|lo]
__device__ __align__(128) __nv_bfloat16 g_wqkv[(size_t)(3*EMB) * 2 * EMB]; // [N][2K] hi|lo
__device__ __align__(128) __nv_bfloat16 g_wp  [(size_t)EMB * 2 * EMB];
__device__ __align__(128) __nv_bfloat16 g_w1  [(size_t)FF  * 2 * EMB];
__device__ __align__(128) __nv_bfloat16 g_w2  [(size_t)EMB * 2 * FF];

// ---------------- PTX helpers (portable: sm_80/90 features only) ----------------
__device__ __forceinline__ uint32_t smem_u32(const void* p) {
    uint32_t a;
    asm("{ .reg .u64 t; cvta.to.shared.u64 t, %1; cvt.u32.u64 %0, t; }" : "=r"(a) : "l"(p));
    return a;
}
#define CPASYNC16(dst, src) asm volatile("cp.async.cg.shared.global [%0], [%1], 16;" :: "r"(dst), "l"(src) : "memory")
#define CP_COMMIT()         asm volatile("cp.async.commit_group;" ::: "memory")
#define CP_WAIT2()          asm volatile("cp.async.wait_group 2;" ::: "memory")

#define LDSM4(r, addr) \
    asm volatile("ldmatrix.sync.aligned.m8n8.x4.shared.b16 {%0,%1,%2,%3}, [%4];" \
        : "=r"((r)[0]), "=r"((r)[1]), "=r"((r)[2]), "=r"((r)[3]) : "r"(addr))

#define MMA16816(d, a, b0, b1) \
    asm volatile("mma.sync.aligned.m16n8k16.row.col.f32.bf16.bf16.f32 " \
        "{%0,%1,%2,%3}, {%4,%5,%6,%7}, {%8,%9}, {%0,%1,%2,%3};" \
        : "+f"((d)[0]), "+f"((d)[1]), "+f"((d)[2]), "+f"((d)[3]) \
        : "r"((a)[0]), "r"((a)[1]), "r"((a)[2]), "r"((a)[3]), "r"(b0), "r"(b1))

__device__ __forceinline__ __nv_bfloat16 bf_hi(float v) { return __float2bfloat16(v); }
__device__ __forceinline__ __nv_bfloat16 bf_lo(float v, __nv_bfloat16 hi) {
    return __float2bfloat16(v - __bfloat162float(hi));
}

// ---------------- weight prep ----------------
__global__ void prep_w_kernel(const float* __restrict__ W, __nv_bfloat16* __restrict__ out,
                              int K, int N) {
    int i = blockIdx.x * blockDim.x + threadIdx.x;
    if (i >= K * N) return;
    int k = i / N, n = i % N;
    float v = W[i];
    __nv_bfloat16 hi = bf_hi(v);
    out[(size_t)n * 2 * K + k]     = hi;
    out[(size_t)n * 2 * K + K + k] = bf_lo(v, hi);
}
__global__ void prep_wqkv_kernel(const float* __restrict__ Wq, const float* __restrict__ Wk,
                                 const float* __restrict__ Wv) {
    int i = blockIdx.x * blockDim.x + threadIdx.x;
    if (i >= NHEAD * EMB * HSZ) return;
    int h = i / (EMB * HSZ), r = i % (EMB * HSZ), c = r / HSZ, d = r % HSZ;
    int n = h * HSZ + d;
    float q = Wq[i], k = Wk[i], v = Wv[i];
    __nv_bfloat16 qh = bf_hi(q), kh = bf_hi(k), vh = bf_hi(v);
    size_t rq = (size_t)n * 2 * EMB, rk = (size_t)(EMB + n) * 2 * EMB, rv = (size_t)(2 * EMB + n) * 2 * EMB;
    g_wqkv[rq + c] = qh;  g_wqkv[rq + EMB + c] = bf_lo(q, qh);
    g_wqkv[rk + c] = kh;  g_wqkv[rk + EMB + c] = bf_lo(k, kh);
    g_wqkv[rv + c] = vh;  g_wqkv[rv + EMB + c] = bf_lo(v, vh);
}

// ---------------- layernorm -> split bf16 [hi|lo] ----------------
__global__ void ln_split_kernel(const float* __restrict__ in, const float* __restrict__ g,
                                const float* __restrict__ b, __nv_bfloat16* __restrict__ out) {
    int row = blockIdx.x;
    int t = threadIdx.x;  // 0..95
    float4 v = ((const float4*)(in + (size_t)row * EMB))[t];
    float s  = v.x + v.y + v.z + v.w;
    float ss = v.x * v.x + v.y * v.y + v.z * v.z + v.w * v.w;
    #pragma unroll
    for (int off = 16; off > 0; off >>= 1) {
        s  += __shfl_down_sync(0xffffffffu, s, off);
        ss += __shfl_down_sync(0xffffffffu, ss, off);
    }
    __shared__ float red0[3], red1[3];
    int w = t >> 5, l = t & 31;
    if (l == 0) { red0[w] = s; red1[w] = ss; }
    __syncthreads();
    float S = red0[0] + red0[1] + red0[2];
    float SS = red1[0] + red1[1] + red1[2];
    float mu = S * (1.0f / EMB);
    float var = SS * (1.0f / EMB) - mu * mu;
    float rs = rsqrtf(var + 1e-5f);
    float4 gv = ((const float4*)g)[t];
    float4 bv = ((const float4*)b)[t];
    float o[4] = {(v.x - mu) * rs * gv.x + bv.x, (v.y - mu) * rs * gv.y + bv.y,
                  (v.z - mu) * rs * gv.z + bv.z, (v.w - mu) * rs * gv.w + bv.w};
    __nv_bfloat16* orow = out + (size_t)row * 2 * EMB;
    __nv_bfloat162 hi2[2], lo2[2];
    #pragma unroll
    for (int j = 0; j < 2; j++) {
        __nv_bfloat16 h0 = bf_hi(o[2 * j]), h1 = bf_hi(o[2 * j + 1]);
        hi2[j] = __nv_bfloat162(h0, h1);
        lo2[j] = __nv_bfloat162(bf_lo(o[2 * j], h0), bf_lo(o[2 * j + 1], h1));
    }
    *(uint2*)(orow + 4 * t)       = *(uint2*)hi2;
    *(uint2*)(orow + EMB + 4 * t) = *(uint2*)lo2;
}

// ---------------- warp-MMA split-bf16 GEMM ----------------
// C[M,N] = A[M,K] @ B[N,K]^T, A/B stored [rows][2K] bf16 (hi|lo).
// BM=BN=128, BK=64, 256 threads, warp grid 4(M)x2(N), warp tile 32x64.
// 3 MMA passes: Ah*Bh + Ah*Bl + Al*Bh. 3-stage cp.async pipeline.
// SMEM rows padded to 144B (9 x 16B chunks) -> conflict-free ldmatrix.
// MODE 0: fp32 out.  MODE 1: fp32 out = acc + bias + res.
// MODE 2: bf16 hi/lo out of relu(acc + bias), row stride 2*Ntot.
constexpr int PIECE  = 128 * 144;        // 18432 bytes per operand piece
constexpr int STAGE  = 4 * PIECE;        // Ah, Al, Bh, Bl
constexpr int GSMEM  = 3 * STAGE;        // 221184

template<int MODE>
__global__ void __launch_bounds__(256, 1)
gemm_tc(const __nv_bfloat16* __restrict__ A, const __nv_bfloat16* __restrict__ B,
        const float* __restrict__ bias, const float* __restrict__ res,
        void* __restrict__ out, int Kw, int Ntot) {
    extern __shared__ char smem[];
    const uint32_t sbase = smem_u32(smem);
    const int tid = threadIdx.x, lane = tid & 31, wid = tid >> 5;
    const int wm = wid >> 1, wn = wid & 1;
    const int m0 = blockIdx.y * 128, n0 = blockIdx.x * 128;
    const int nstages = Kw >> 6;

    const int lrow = tid >> 1, lhalf = tid & 1;   // loader mapping
    const __nv_bfloat16* agp = A + (size_t)(m0 + lrow) * (2 * Kw) + lhalf * 32;
    const __nv_bfloat16* bgp = B + (size_t)(n0 + lrow) * (2 * Kw) + lhalf * 32;
    const uint32_t ldst = (uint32_t)(lrow * 144 + lhalf * 64);

    // ---- pipeline load helper (macro to avoid lambda overhead) ----
#define LOAD_STAGE(bufi, k0v) do { \
        const uint32_t sb = sbase + (bufi) * STAGE; \
        const __nv_bfloat16* a0p = agp + (k0v); \
        const __nv_bfloat16* b0p = bgp + (k0v); \
        uint32_t d0 = sb + ldst; \
        CPASYNC16(d0 +  0, a0p);      CPASYNC16(d0 + 16, a0p + 8); \
        CPASYNC16(d0 + 32, a0p + 16); CPASYNC16(d0 + 48, a0p + 24); \
        d0 += PIECE; a0p += Kw; \
        CPASYNC16(d0 +  0, a0p);      CPASYNC16(d0 + 16, a0p + 8); \
        CPASYNC16(d0 + 32, a0p + 16); CPASYNC16(d0 + 48, a0p + 24); \
        d0 = sb + 2 * PIECE + ldst; \
        CPASYNC16(d0 +  0, b0p);      CPASYNC16(d0 + 16, b0p + 8); \
        CPASYNC16(d0 + 32, b0p + 16); CPASYNC16(d0 + 48, b0p + 24); \
        d0 += PIECE; b0p += Kw; \
        CPASYNC16(d0 +  0, b0p);      CPASYNC16(d0 + 16, b0p + 8); \
        CPASYNC16(d0 + 32, b0p + 16); CPASYNC16(d0 + 48, b0p + 24); \
    } while (0)

    float d[2][8][4];
    #pragma unroll
    for (int i = 0; i < 2; i++)
        #pragma unroll
        for (int j = 0; j < 8; j++)
            #pragma unroll
            for (int q = 0; q < 4; q++) d[i][j][q] = 0.0f;

    // ldmatrix source addresses
    const uint32_t a_off = (uint32_t)((wm * 32 + (lane & 15)) * 144 + (lane >> 4) * 16);
    const int nl = (lane & 7) + ((lane >> 4) << 3);
    const int kc = (lane >> 3) & 1;
    const uint32_t b_off = (uint32_t)((wn * 64 + nl) * 144 + kc * 16);

    // prologue: stages 0,1
    LOAD_STAGE(0, 0);  CP_COMMIT();
    LOAD_STAGE(1, 64); CP_COMMIT();

    for (int it = 0; it < nstages; it++) {
        if (it + 2 < nstages) LOAD_STAGE((it + 2) % 3, (it + 2) * 64);
        CP_COMMIT();
        CP_WAIT2();
        __syncthreads();

        const uint32_t sA = sbase + (it % 3) * STAGE;
        const uint32_t sB = sA + 2 * PIECE;
        #pragma unroll
        for (int kk = 0; kk < 4; kk++) {
            uint32_t a[2][2][4];   // [split][mi]
            uint32_t b[2][4][4];   // [split][npair]
            #pragma unroll
            for (int sp = 0; sp < 2; sp++)
                #pragma unroll
                for (int mi = 0; mi < 2; mi++)
                    LDSM4(a[sp][mi], sA + sp * PIECE + a_off + mi * (16 * 144) + kk * 32);
            #pragma unroll
            for (int sp = 0; sp < 2; sp++)
                #pragma unroll
                for (int np = 0; np < 4; np++)
                    LDSM4(b[sp][np], sB + sp * PIECE + b_off + np * (16 * 144) + kk * 32);
            #pragma unroll
            for (int mi = 0; mi < 2; mi++)
                #pragma unroll
                for (int np = 0; np < 4; np++)
                    #pragma unroll
                    for (int sub = 0; sub < 2; sub++) {
                        int ni = np * 2 + sub;
                        MMA16816(d[mi][ni], a[0][mi], b[0][np][sub*2], b[0][np][sub*2+1]); // hi*hi
                        MMA16816(d[mi][ni], a[0][mi], b[1][np][sub*2], b[1][np][sub*2+1]); // hi*lo
                        MMA16816(d[mi][ni], a[1][mi], b[0][np][sub*2], b[0][np][sub*2+1]); // lo*hi
                    }
        }
        __syncthreads();
    }
#undef LOAD_STAGE

    // ---- epilogue ----
    #pragma unroll
    for (int mi = 0; mi < 2; mi++) {
        int row0 = m0 + wm * 32 + mi * 16 + (lane >> 2);
        #pragma unroll
        for (int ni = 0; ni < 8; ni++) {
            int col = n0 + wn * 64 + ni * 8 + (lane & 3) * 2;
            if (MODE == 0) {
                float* o = (float*)out;
                *(float2*)(o + (size_t)row0 * Ntot + col)       = make_float2(d[mi][ni][0], d[mi][ni][1]);
                *(float2*)(o + (size_t)(row0 + 8) * Ntot + col) = make_float2(d[mi][ni][2], d[mi][ni][3]);
            } else if (MODE == 1) {
                float b0 = bias[col], b1 = bias[col + 1];
                float* o = (float*)out;
                float2 r0 = *(const float2*)(res + (size_t)row0 * Ntot + col);
                float2 r1 = *(const float2*)(res + (size_t)(row0 + 8) * Ntot + col);
                *(float2*)(o + (size_t)row0 * Ntot + col) =
                    make_float2(d[mi][ni][0] + b0 + r0.x, d[mi][ni][1] + b1 + r0.y);
                *(float2*)(o + (size_t)(row0 + 8) * Ntot + col) =
                    make_float2(d[mi][ni][2] + b0 + r1.x, d[mi][ni][3] + b1 + r1.y);
            } else {
                float b0 = bias[col], b1 = bias[col + 1];
                __nv_bfloat16* ob = (__nv_bfloat16*)out;
                #pragma unroll
                for (int rr = 0; rr < 2; rr++) {
                    int row = row0 + rr * 8;
                    float v0 = fmaxf(d[mi][ni][2 * rr]     + b0, 0.0f);
                    float v1 = fmaxf(d[mi][ni][2 * rr + 1] + b1, 0.0f);
                    __nv_bfloat16 h0 = bf_hi(v0), h1 = bf_hi(v1);
                    __nv_bfloat16* orow = ob + (size_t)row * (2 * Ntot);
                    *(__nv_bfloat162*)(orow + col)        = __nv_bfloat162(h0, h1);
                    *(__nv_bfloat162*)(orow + Ntot + col) = __nv_bfloat162(bf_lo(v0, h0), bf_lo(v1, h1));
                }
            }
        }
    }
}

// ---------------- attention (fp32 in, split-bf16 out) ----------------
__global__ void attn_kernel(const float* __restrict__ qkv, __nv_bfloat16* __restrict__ out) {
    int b = blockIdx.x, h = blockIdx.y;
    int t = threadIdx.x;
    __shared__ float ks[SEQ][HSZ];
    __shared__ float vs[SEQ][HSZ];
    __shared__ float ps[SEQ][SEQ + 1];

    const float* base = qkv + (size_t)(b * SEQ + t) * (3 * EMB) + h * HSZ;
    float qreg[HSZ];
    #pragma unroll
    for (int i = 0; i < HSZ / 4; i++) {
        float4 qv = *(const float4*)(base + i * 4);
        qreg[4*i] = qv.x; qreg[4*i+1] = qv.y; qreg[4*i+2] = qv.z; qreg[4*i+3] = qv.w;
        *(float4*)(&ks[t][4*i]) = *(const float4*)(base + EMB + i * 4);
        *(float4*)(&vs[t][4*i]) = *(const float4*)(base + 2 * EMB + i * 4);
    }
    __syncthreads();
    float mx = -1e30f;
    for (int s = 0; s <= t; s++) {
        float acc = 0.0f;
        #pragma unroll
        for (int dd = 0; dd < HSZ; dd++) acc += qreg[dd] * ks[s][dd];
        acc *= ATT_SCALE;
        ps[t][s] = acc;
        mx = fmaxf(mx, acc);
    }
    float sum = 0.0f;
    for (int s = 0; s <= t; s++) {
        float e = __expf(ps[t][s] - mx);
        ps[t][s] = e;
        sum += e;
    }
    float inv = 1.0f / sum;
    float oacc[HSZ];
    #pragma unroll
    for (int dd = 0; dd < HSZ; dd++) oacc[dd] = 0.0f;
    for (int s = 0; s <= t; s++) {
        float p = ps[t][s] * inv;
        #pragma unroll
        for (int dd = 0; dd < HSZ; dd++) oacc[dd] += p * vs[s][dd];
    }
    __nv_bfloat16* op = out + (size_t)(b * SEQ + t) * (2 * EMB) + h * HSZ;
    #pragma unroll
    for (int i = 0; i < HSZ / 2; i++) {
        float v0 = oacc[2*i], v1 = oacc[2*i+1];
        __nv_bfloat16 h0 = bf_hi(v0), h1 = bf_hi(v1);
        *(__nv_bfloat162*)(op + 2*i)       = __nv_bfloat162(h0, h1);
        *(__nv_bfloat162*)(op + EMB + 2*i) = __nv_bfloat162(bf_lo(v0,h0), bf_lo(v1,h1));
    }
}

// ---------------- launch ----------------
extern "C" void kernel_launch(void* const* d_in, const int* in_sizes, int n_in,
                              void* d_out, int out_size) {
    const float* x     = (const float*)d_in[0];
    const float* ln1_g = (const float*)d_in[1];
    const float* ln1_b = (const float*)d_in[2];
    const float* ln2_g = (const float*)d_in[3];
    const float* ln2_b = (const float*)d_in[4];
    const float* Wq    = (const float*)d_in[5];
    const float* Wk    = (const float*)d_in[6];
    const float* Wv    = (const float*)d_in[7];
    const float* Wp    = (const float*)d_in[8];
    const float* bp    = (const float*)d_in[9];
    const float* W1    = (const float*)d_in[10];
    const float* b1    = (const float*)d_in[11];
    const float* W2    = (const float*)d_in[12];
    const float* b2    = (const float*)d_in[13];
    float* out = (float*)d_out;

    __nv_bfloat16 *ln1, *attn, *h2, *hid, *wqkv, *wp, *w1, *w2;
    float *qkv, *x2;
    cudaGetSymbolAddress((void**)&ln1,  g_ln1);
    cudaGetSymbolAddress((void**)&qkv,  g_qkv);
    cudaGetSymbolAddress((void**)&attn, g_attn);
    cudaGetSymbolAddress((void**)&x2,   g_x2);
    cudaGetSymbolAddress((void**)&h2,   g_h2);
    cudaGetSymbolAddress((void**)&hid,  g_hid);
    cudaGetSymbolAddress((void**)&wqkv, g_wqkv);
    cudaGetSymbolAddress((void**)&wp,   g_wp);
    cudaGetSymbolAddress((void**)&w1,   g_w1);
    cudaGetSymbolAddress((void**)&w2,   g_w2);

    cudaFuncSetAttribute(gemm_tc<0>, cudaFuncAttributeMaxDynamicSharedMemorySize, GSMEM);
    cudaFuncSetAttribute(gemm_tc<1>, cudaFuncAttributeMaxDynamicSharedMemorySize, GSMEM);
    cudaFuncSetAttribute(gemm_tc<2>, cudaFuncAttributeMaxDynamicSharedMemorySize, GSMEM);

    // weight prep
    prep_wqkv_kernel<<<(NHEAD * EMB * HSZ + 255) / 256, 256>>>(Wq, Wk, Wv);
    prep_w_kernel<<<(EMB * EMB + 255) / 256, 256>>>(Wp, wp, EMB, EMB);
    prep_w_kernel<<<(EMB * FF + 255) / 256, 256>>>(W1, w1, EMB, FF);
    prep_w_kernel<<<(FF * EMB + 255) / 256, 256>>>(W2, w2, FF, EMB);

    // 1) LN1 -> split bf16
    ln_split_kernel<<<N_TOK, 96>>>(x, ln1_g, ln1_b, ln1);
    // 2) QKV GEMM -> fp32 qkv
    gemm_tc<0><<<dim3(9, N_TOK / 128), 256, GSMEM>>>(ln1, wqkv, nullptr, nullptr, qkv, EMB, 3 * EMB);
    // 3) attention -> split bf16
    attn_kernel<<<dim3(2048, NHEAD), SEQ>>>(qkv, attn);
    // 4) proj + bias + residual(x) -> fp32 x2
    gemm_tc<1><<<dim3(3, N_TOK / 128), 256, GSMEM>>>(attn, wp, bp, x, x2, EMB, EMB);
    // 5) LN2 -> split bf16
    ln_split_kernel<<<N_TOK, 96>>>(x2, ln2_g, ln2_b, h2);
    // 6) MLP up + relu -> split bf16 hidden
    gemm_tc<2><<<dim3(12, N_TOK / 128), 256, GSMEM>>>(h2, w1, b1, nullptr, hid, EMB, FF);
    // 7) MLP down + bias + residual(x2) -> out
    gemm_tc<1><<<dim3(3, N_TOK / 128), 256, GSMEM>>>(hid, w2, b2, x2, out, FF, EMB);
}

// round 4
// speedup vs baseline: 1.9584x; 1.0689x over previous
#include <cuda_runtime.h>
#include <cuda_bf16.h>
#include <cstdint>

// ---------------- problem constants ----------------
constexpr int N_TOK  = 2048 * 64;   // 131072 tokens
constexpr int EMB    = 384;
constexpr int NHEAD  = 8;
constexpr int HSZ    = 48;
constexpr int SEQ    = 64;
constexpr int FF     = 1536;
constexpr float ATT_SCALE = 2.449489742783178f;

// ---------------- scratch (static device memory) ----------------
__device__ __align__(128) __nv_bfloat16 g_ln1 [(size_t)N_TOK * 2 * EMB];   // [hi|lo]
__device__ __align__(128) float         g_qkv [(size_t)N_TOK * 3 * EMB];   // fp32 q|k|v
__device__ __align__(128) __nv_bfloat16 g_attn[(size_t)N_TOK * 2 * EMB];   // [hi|lo]
__device__ __align__(128) float         g_x2  [(size_t)N_TOK * EMB];       // fp32 residual
__device__ __align__(128) __nv_bfloat16 g_h2  [(size_t)N_TOK * 2 * EMB];   // [hi|lo]
__device__ __align__(128) __nv_bfloat16 g_hid [(size_t)N_TOK * 2 * FF];    // [hi|lo]
__device__ __align__(128) __nv_bfloat16 g_wqkv[(size_t)(3*EMB) * 2 * EMB]; // [N][2K] hi|lo
__device__ __align__(128) __nv_bfloat16 g_wp  [(size_t)EMB * 2 * EMB];
__device__ __align__(128) __nv_bfloat16 g_w1  [(size_t)FF  * 2 * EMB];
__device__ __align__(128) __nv_bfloat16 g_w2  [(size_t)EMB * 2 * FF];

// ---------------- PTX helpers (portable: sm_80/90 features only) ----------------
__device__ __forceinline__ uint32_t smem_u32(const void* p) {
    uint32_t a;
    asm("{ .reg .u64 t; cvta.to.shared.u64 t, %1; cvt.u32.u64 %0, t; }" : "=r"(a) : "l"(p));
    return a;
}
#define CPASYNC16(dst, src) asm volatile("cp.async.cg.shared.global [%0], [%1], 16;" :: "r"(dst), "l"(src) : "memory")
#define CP_COMMIT()         asm volatile("cp.async.commit_group;" ::: "memory")
#define CP_WAIT1()          asm volatile("cp.async.wait_group 1;" ::: "memory")

#define LDSM4(r, addr) \
    asm volatile("ldmatrix.sync.aligned.m8n8.x4.shared.b16 {%0,%1,%2,%3}, [%4];" \
        : "=r"((r)[0]), "=r"((r)[1]), "=r"((r)[2]), "=r"((r)[3]) : "r"(addr))

#define MMA16816(d, a, b0, b1) \
    asm volatile("mma.sync.aligned.m16n8k16.row.col.f32.bf16.bf16.f32 " \
        "{%0,%1,%2,%3}, {%4,%5,%6,%7}, {%8,%9}, {%0,%1,%2,%3};" \
        : "+f"((d)[0]), "+f"((d)[1]), "+f"((d)[2]), "+f"((d)[3]) \
        : "r"((a)[0]), "r"((a)[1]), "r"((a)[2]), "r"((a)[3]), "r"(b0), "r"(b1))

__device__ __forceinline__ __nv_bfloat16 bf_hi(float v) { return __float2bfloat16(v); }
__device__ __forceinline__ __nv_bfloat16 bf_lo(float v, __nv_bfloat16 hi) {
    return __float2bfloat16(v - __bfloat162float(hi));
}

// ---------------- weight prep ----------------
__global__ void prep_w_kernel(const float* __restrict__ W, __nv_bfloat16* __restrict__ out,
                              int K, int N) {
    int i = blockIdx.x * blockDim.x + threadIdx.x;
    if (i >= K * N) return;
    int k = i / N, n = i % N;
    float v = W[i];
    __nv_bfloat16 hi = bf_hi(v);
    out[(size_t)n * 2 * K + k]     = hi;
    out[(size_t)n * 2 * K + K + k] = bf_lo(v, hi);
}
__global__ void prep_wqkv_kernel(const float* __restrict__ Wq, const float* __restrict__ Wk,
                                 const float* __restrict__ Wv) {
    int i = blockIdx.x * blockDim.x + threadIdx.x;
    if (i >= NHEAD * EMB * HSZ) return;
    int h = i / (EMB * HSZ), r = i % (EMB * HSZ), c = r / HSZ, d = r % HSZ;
    int n = h * HSZ + d;
    float q = Wq[i], k = Wk[i], v = Wv[i];
    __nv_bfloat16 qh = bf_hi(q), kh = bf_hi(k), vh = bf_hi(v);
    size_t rq = (size_t)n * 2 * EMB, rk = (size_t)(EMB + n) * 2 * EMB, rv = (size_t)(2 * EMB + n) * 2 * EMB;
    g_wqkv[rq + c] = qh;  g_wqkv[rq + EMB + c] = bf_lo(q, qh);
    g_wqkv[rk + c] = kh;  g_wqkv[rk + EMB + c] = bf_lo(k, kh);
    g_wqkv[rv + c] = vh;  g_wqkv[rv + EMB + c] = bf_lo(v, vh);
}

// ---------------- layernorm -> split bf16 [hi|lo] ----------------
__global__ void ln_split_kernel(const float* __restrict__ in, const float* __restrict__ g,
                                const float* __restrict__ b, __nv_bfloat16* __restrict__ out) {
    int row = blockIdx.x;
    int t = threadIdx.x;  // 0..95
    float4 v = ((const float4*)(in + (size_t)row * EMB))[t];
    float s  = v.x + v.y + v.z + v.w;
    float ss = v.x * v.x + v.y * v.y + v.z * v.z + v.w * v.w;
    #pragma unroll
    for (int off = 16; off > 0; off >>= 1) {
        s  += __shfl_down_sync(0xffffffffu, s, off);
        ss += __shfl_down_sync(0xffffffffu, ss, off);
    }
    __shared__ float red0[3], red1[3];
    int w = t >> 5, l = t & 31;
    if (l == 0) { red0[w] = s; red1[w] = ss; }
    __syncthreads();
    float S = red0[0] + red0[1] + red0[2];
    float SS = red1[0] + red1[1] + red1[2];
    float mu = S * (1.0f / EMB);
    float var = SS * (1.0f / EMB) - mu * mu;
    float rs = rsqrtf(var + 1e-5f);
    float4 gv = ((const float4*)g)[t];
    float4 bv = ((const float4*)b)[t];
    float o[4] = {(v.x - mu) * rs * gv.x + bv.x, (v.y - mu) * rs * gv.y + bv.y,
                  (v.z - mu) * rs * gv.z + bv.z, (v.w - mu) * rs * gv.w + bv.w};
    __nv_bfloat16* orow = out + (size_t)row * 2 * EMB;
    __nv_bfloat162 hi2[2], lo2[2];
    #pragma unroll
    for (int j = 0; j < 2; j++) {
        __nv_bfloat16 h0 = bf_hi(o[2 * j]), h1 = bf_hi(o[2 * j + 1]);
        hi2[j] = __nv_bfloat162(h0, h1);
        lo2[j] = __nv_bfloat162(bf_lo(o[2 * j], h0), bf_lo(o[2 * j + 1], h1));
    }
    *(uint2*)(orow + 4 * t)       = *(uint2*)hi2;
    *(uint2*)(orow + EMB + 4 * t) = *(uint2*)lo2;
}

// ---------------- warp-MMA split-bf16 GEMM ----------------
// C[M,N] = A[M,K] @ B[N,K]^T, A/B stored [rows][2K] bf16 (hi|lo).
// BM=BN=128, BK=64, 256 threads, warp grid 4(M)x2(N), warp tile 32x64.
// 3 MMA passes pass-major (no accumulator RAW chains). 3-stage cp.async ring,
// ONE __syncthreads per stage. 144B-padded rows -> conflict-free ldmatrix.
constexpr int PIECE  = 128 * 144;        // 18432 bytes per operand piece
constexpr int STAGE  = 4 * PIECE;        // Ah, Al, Bh, Bl
constexpr int GSMEM  = 3 * STAGE;        // 221184

template<int MODE>
__global__ void __launch_bounds__(256, 1)
gemm_tc(const __nv_bfloat16* __restrict__ A, const __nv_bfloat16* __restrict__ B,
        const float* __restrict__ bias, const float* __restrict__ res,
        void* __restrict__ out, int Kw, int Ntot) {
    extern __shared__ char smem[];
    const uint32_t sbase = smem_u32(smem);
    const int tid = threadIdx.x, lane = tid & 31, wid = tid >> 5;
    const int wm = wid >> 1, wn = wid & 1;
    const int m0 = blockIdx.y * 128, n0 = blockIdx.x * 128;
    const int nstages = Kw >> 6;

    const int lrow = tid >> 1, lhalf = tid & 1;   // loader mapping
    const __nv_bfloat16* agp = A + (size_t)(m0 + lrow) * (2 * Kw) + lhalf * 32;
    const __nv_bfloat16* bgp = B + (size_t)(n0 + lrow) * (2 * Kw) + lhalf * 32;
    const uint32_t ldst = (uint32_t)(lrow * 144 + lhalf * 64);

#define LOAD_STAGE(bufi, k0v) do { \
        const uint32_t sb = sbase + (bufi) * STAGE; \
        const __nv_bfloat16* a0p = agp + (k0v); \
        const __nv_bfloat16* b0p = bgp + (k0v); \
        uint32_t d0 = sb + ldst; \
        CPASYNC16(d0 +  0, a0p);      CPASYNC16(d0 + 16, a0p + 8); \
        CPASYNC16(d0 + 32, a0p + 16); CPASYNC16(d0 + 48, a0p + 24); \
        d0 += PIECE; a0p += Kw; \
        CPASYNC16(d0 +  0, a0p);      CPASYNC16(d0 + 16, a0p + 8); \
        CPASYNC16(d0 + 32, a0p + 16); CPASYNC16(d0 + 48, a0p + 24); \
        d0 = sb + 2 * PIECE + ldst; \
        CPASYNC16(d0 +  0, b0p);      CPASYNC16(d0 + 16, b0p + 8); \
        CPASYNC16(d0 + 32, b0p + 16); CPASYNC16(d0 + 48, b0p + 24); \
        d0 += PIECE; b0p += Kw; \
        CPASYNC16(d0 +  0, b0p);      CPASYNC16(d0 + 16, b0p + 8); \
        CPASYNC16(d0 + 32, b0p + 16); CPASYNC16(d0 + 48, b0p + 24); \
    } while (0)

    float d[2][8][4];
    #pragma unroll
    for (int i = 0; i < 2; i++)
        #pragma unroll
        for (int j = 0; j < 8; j++)
            #pragma unroll
            for (int q = 0; q < 4; q++) d[i][j][q] = 0.0f;

    const uint32_t a_off = (uint32_t)((wm * 32 + (lane & 15)) * 144 + (lane >> 4) * 16);
    const int nl = (lane & 7) + ((lane >> 4) << 3);
    const int kc = (lane >> 3) & 1;
    const uint32_t b_off = (uint32_t)((wn * 64 + nl) * 144 + kc * 16);

    // prologue: stages 0,1
    LOAD_STAGE(0, 0);  CP_COMMIT();
    LOAD_STAGE(1, 64); CP_COMMIT();

    for (int it = 0; it < nstages; it++) {
        CP_WAIT1();
        __syncthreads();
        if (it + 2 < nstages) LOAD_STAGE((it + 2) % 3, (it + 2) * 64);
        CP_COMMIT();

        const uint32_t sA = sbase + (it % 3) * STAGE;
        const uint32_t sB = sA + 2 * PIECE;
        #pragma unroll
        for (int kk = 0; kk < 4; kk++) {
            uint32_t a[2][2][4];   // [split][mi]
            uint32_t b[2][4][4];   // [split][npair]
            #pragma unroll
            for (int sp = 0; sp < 2; sp++)
                #pragma unroll
                for (int mi = 0; mi < 2; mi++)
                    LDSM4(a[sp][mi], sA + sp * PIECE + a_off + mi * (16 * 144) + kk * 32);
            #pragma unroll
            for (int sp = 0; sp < 2; sp++)
                #pragma unroll
                for (int np = 0; np < 4; np++)
                    LDSM4(b[sp][np], sB + sp * PIECE + b_off + np * (16 * 144) + kk * 32);
            // pass-major: accumulator reuse distance = 16 MMAs
            #pragma unroll
            for (int mi = 0; mi < 2; mi++)
                #pragma unroll
                for (int np = 0; np < 4; np++)
                    #pragma unroll
                    for (int sub = 0; sub < 2; sub++)
                        MMA16816(d[mi][np * 2 + sub], a[0][mi], b[0][np][sub*2], b[0][np][sub*2+1]);
            #pragma unroll
            for (int mi = 0; mi < 2; mi++)
                #pragma unroll
                for (int np = 0; np < 4; np++)
                    #pragma unroll
                    for (int sub = 0; sub < 2; sub++)
                        MMA16816(d[mi][np * 2 + sub], a[0][mi], b[1][np][sub*2], b[1][np][sub*2+1]);
            #pragma unroll
            for (int mi = 0; mi < 2; mi++)
                #pragma unroll
                for (int np = 0; np < 4; np++)
                    #pragma unroll
                    for (int sub = 0; sub < 2; sub++)
                        MMA16816(d[mi][np * 2 + sub], a[1][mi], b[0][np][sub*2], b[0][np][sub*2+1]);
        }
    }
#undef LOAD_STAGE

    // ---- epilogue ----
    #pragma unroll
    for (int mi = 0; mi < 2; mi++) {
        int row0 = m0 + wm * 32 + mi * 16 + (lane >> 2);
        #pragma unroll
        for (int ni = 0; ni < 8; ni++) {
            int col = n0 + wn * 64 + ni * 8 + (lane & 3) * 2;
            if (MODE == 0) {
                float* o = (float*)out;
                *(float2*)(o + (size_t)row0 * Ntot + col)       = make_float2(d[mi][ni][0], d[mi][ni][1]);
                *(float2*)(o + (size_t)(row0 + 8) * Ntot + col) = make_float2(d[mi][ni][2], d[mi][ni][3]);
            } else if (MODE == 1) {
                float b0 = bias[col], b1 = bias[col + 1];
                float* o = (float*)out;
                float2 r0 = *(const float2*)(res + (size_t)row0 * Ntot + col);
                float2 r1 = *(const float2*)(res + (size_t)(row0 + 8) * Ntot + col);
                *(float2*)(o + (size_t)row0 * Ntot + col) =
                    make_float2(d[mi][ni][0] + b0 + r0.x, d[mi][ni][1] + b1 + r0.y);
                *(float2*)(o + (size_t)(row0 + 8) * Ntot + col) =
                    make_float2(d[mi][ni][2] + b0 + r1.x, d[mi][ni][3] + b1 + r1.y);
            } else {
                float b0 = bias[col], b1 = bias[col + 1];
                __nv_bfloat16* ob = (__nv_bfloat16*)out;
                #pragma unroll
                for (int rr = 0; rr < 2; rr++) {
                    int row = row0 + rr * 8;
                    float v0 = fmaxf(d[mi][ni][2 * rr]     + b0, 0.0f);
                    float v1 = fmaxf(d[mi][ni][2 * rr + 1] + b1, 0.0f);
                    __nv_bfloat16 h0 = bf_hi(v0), h1 = bf_hi(v1);
                    __nv_bfloat16* orow = ob + (size_t)row * (2 * Ntot);
                    *(__nv_bfloat162*)(orow + col)        = __nv_bfloat162(h0, h1);
                    *(__nv_bfloat162*)(orow + Ntot + col) = __nv_bfloat162(bf_lo(v0, h0), bf_lo(v1, h1));
                }
            }
        }
    }
}

// ---------------- attention: online block softmax, 128 thr = 64 rows x 2 halves ----------------
__global__ void __launch_bounds__(128)
attn_kernel(const float* __restrict__ qkv, __nv_bfloat16* __restrict__ out) {
    const int b = blockIdx.x, h = blockIdx.y;
    const int tid = threadIdx.x;
    const int r = tid >> 1, half = tid & 1;
    __shared__ float ks[SEQ][HSZ];
    __shared__ float vs[SEQ][HSZ];

    // cooperative K/V load (float4)
    for (int i = tid; i < SEQ * (HSZ / 4); i += 128) {
        int s = i / (HSZ / 4), c = i % (HSZ / 4);
        const float* src = qkv + (size_t)(b * SEQ + s) * (3 * EMB) + h * HSZ;
        *(float4*)&ks[s][c * 4] = *(const float4*)(src + EMB + c * 4);
        *(float4*)&vs[s][c * 4] = *(const float4*)(src + 2 * EMB + c * 4);
    }
    // q for (row r, half): 24 floats
    float q[24];
    {
        const float* qsrc = qkv + (size_t)(b * SEQ + r) * (3 * EMB) + h * HSZ + half * 24;
        #pragma unroll
        for (int i = 0; i < 6; i++) {
            float4 v = *(const float4*)(qsrc + 4 * i);
            q[4*i] = v.x; q[4*i+1] = v.y; q[4*i+2] = v.z; q[4*i+3] = v.w;
        }
    }
    __syncthreads();

    const uint32_t pmask = 3u << ((tid & 31) & ~1);
    float m = -1e30f, l = 0.0f;
    float o[24];
    #pragma unroll
    for (int dd = 0; dd < 24; dd++) o[dd] = 0.0f;

    for (int s0 = 0; s0 <= r; s0 += 16) {
        float sc[16];
        float bm = -1e30f;
        #pragma unroll
        for (int j = 0; j < 16; j++) {
            int s = s0 + j;
            float pd = 0.0f;
            if (s <= r) {
                const float* kp = &ks[s][half * 24];
                #pragma unroll
                for (int dd = 0; dd < 24; dd++) pd += q[dd] * kp[dd];
            }
            pd += __shfl_xor_sync(pmask, pd, 1);
            sc[j] = (s <= r) ? pd * ATT_SCALE : -1e30f;
            bm = fmaxf(bm, sc[j]);
        }
        float nm = fmaxf(m, bm);
        float alpha = __expf(m - nm);
        l *= alpha;
        #pragma unroll
        for (int dd = 0; dd < 24; dd++) o[dd] *= alpha;
        #pragma unroll
        for (int j = 0; j < 16; j++) {
            float p = __expf(sc[j] - nm);
            l += p;
            int sv = s0 + j; sv = sv < SEQ ? sv : SEQ - 1;
            const float* vp = &vs[sv][half * 24];
            #pragma unroll
            for (int dd = 0; dd < 24; dd++) o[dd] += p * vp[dd];
        }
        m = nm;
    }
    float inv = 1.0f / l;
    __nv_bfloat16* op = out + (size_t)(b * SEQ + r) * (2 * EMB) + h * HSZ + half * 24;
    #pragma unroll
    for (int i = 0; i < 12; i++) {
        float v0 = o[2*i] * inv, v1 = o[2*i+1] * inv;
        __nv_bfloat16 h0 = bf_hi(v0), h1 = bf_hi(v1);
        *(__nv_bfloat162*)(op + 2*i)       = __nv_bfloat162(h0, h1);
        *(__nv_bfloat162*)(op + EMB + 2*i) = __nv_bfloat162(bf_lo(v0, h0), bf_lo(v1, h1));
    }
}

// ---------------- launch ----------------
extern "C" void kernel_launch(void* const* d_in, const int* in_sizes, int n_in,
                              void* d_out, int out_size) {
    const float* x     = (const float*)d_in[0];
    const float* ln1_g = (const float*)d_in[1];
    const float* ln1_b = (const float*)d_in[2];
    const float* ln2_g = (const float*)d_in[3];
    const float* ln2_b = (const float*)d_in[4];
    const float* Wq    = (const float*)d_in[5];
    const float* Wk    = (const float*)d_in[6];
    const float* Wv    = (const float*)d_in[7];
    const float* Wp    = (const float*)d_in[8];
    const float* bp    = (const float*)d_in[9];
    const float* W1    = (const float*)d_in[10];
    const float* b1    = (const float*)d_in[11];
    const float* W2    = (const float*)d_in[12];
    const float* b2    = (const float*)d_in[13];
    float* out = (float*)d_out;

    __nv_bfloat16 *ln1, *attn, *h2, *hid, *wqkv, *wp, *w1, *w2;
    float *qkv, *x2;
    cudaGetSymbolAddress((void**)&ln1,  g_ln1);
    cudaGetSymbolAddress((void**)&qkv,  g_qkv);
    cudaGetSymbolAddress((void**)&attn, g_attn);
    cudaGetSymbolAddress((void**)&x2,   g_x2);
    cudaGetSymbolAddress((void**)&h2,   g_h2);
    cudaGetSymbolAddress((void**)&hid,  g_hid);
    cudaGetSymbolAddress((void**)&wqkv, g_wqkv);
    cudaGetSymbolAddress((void**)&wp,   g_wp);
    cudaGetSymbolAddress((void**)&w1,   g_w1);
    cudaGetSymbolAddress((void**)&w2,   g_w2);

    cudaFuncSetAttribute(gemm_tc<0>, cudaFuncAttributeMaxDynamicSharedMemorySize, GSMEM);
    cudaFuncSetAttribute(gemm_tc<1>, cudaFuncAttributeMaxDynamicSharedMemorySize, GSMEM);
    cudaFuncSetAttribute(gemm_tc<2>, cudaFuncAttributeMaxDynamicSharedMemorySize, GSMEM);

    // weight prep
    prep_wqkv_kernel<<<(NHEAD * EMB * HSZ + 255) / 256, 256>>>(Wq, Wk, Wv);
    prep_w_kernel<<<(EMB * EMB + 255) / 256, 256>>>(Wp, wp, EMB, EMB);
    prep_w_kernel<<<(EMB * FF + 255) / 256, 256>>>(W1, w1, EMB, FF);
    prep_w_kernel<<<(FF * EMB + 255) / 256, 256>>>(W2, w2, FF, EMB);

    // 1) LN1 -> split bf16
    ln_split_kernel<<<N_TOK, 96>>>(x, ln1_g, ln1_b, ln1);
    // 2) QKV GEMM -> fp32 qkv
    gemm_tc<0><<<dim3(9, N_TOK / 128), 256, GSMEM>>>(ln1, wqkv, nullptr, nullptr, qkv, EMB, 3 * EMB);
    // 3) attention -> split bf16
    attn_kernel<<<dim3(2048, NHEAD), 128>>>(qkv, attn);
    // 4) proj + bias + residual(x) -> fp32 x2
    gemm_tc<1><<<dim3(3, N_TOK / 128), 256, GSMEM>>>(attn, wp, bp, x, x2, EMB, EMB);
    // 5) LN2 -> split bf16
    ln_split_kernel<<<N_TOK, 96>>>(x2, ln2_g, ln2_b, h2);
    // 6) MLP up + relu -> split bf16 hidden
    gemm_tc<2><<<dim3(12, N_TOK / 128), 256, GSMEM>>>(h2, w1, b1, nullptr, hid, EMB, FF);
    // 7) MLP down + bias + residual(x2) -> out
    gemm_tc<1><<<dim3(3, N_TOK / 128), 256, GSMEM>>>(hid, w2, b2, x2, out, FF, EMB);
}